// round 15
// baseline (speedup 1.0000x reference)
#include <cuda_runtime.h>

#define BB 8192
#define TT 2048
#define NTHREADS 128           // 4 warps/block -> 1 warp per SMSP
#define NBLOCKS  128           // 512 warps; lane pair per chain
#define CHUNK 8                // timesteps per prefetch chunk

#define MAGIC 12582912.0f      // 1.5*2^23 round-to-nearest-int trick
#define NL2E  (-1.4426950408889634f)   // -log2(e)

__device__ __forceinline__ float tanh_ap(float x) {
    float y;
    asm("tanh.approx.f32 %0, %1;" : "=f"(y) : "f"(x));
    return y;
}

// sigma on the FMA/ALU pipes: r = 1/(1+2^zs) with zs = -log2(e)*z folded
// into the weights. Fixed-latency ops only (no MUFU): dependent latency
// ~62-70 cyc AND no rt16 stagger against the other gates. No clamp: the
// exponent bit-injection is valid for |zs| < 126; |z| here is < ~40.
// (Structure validated in R6: rel_err 4.0e-6.)
__device__ __forceinline__ float sigp(float zs) {
    const float tb = zs + MAGIC;              // low mantissa = round(zs)
    const float rz = tb - MAGIC;
    const float f  = zs - rz;                 // frac in [-0.5, 0.5]
    const float f2 = f * f;
    const float pa = fmaf(0.0013333558f, f, 0.009618129f);
    const float pb = fmaf(0.055504109f,  f, 0.24022651f);
    const float pc = fmaf(0.69314718f,   f, 1.0f);
    const float q  = fmaf(pa, f2, pb);
    const float p  = fmaf(q,  f2, pc);        // 2^f, rel err ~2.4e-6
    const int  ib  = (__float_as_int(tb) << 23) + 0x3F800000;
    const float e  = p * __int_as_float(ib);  // 2^zs
    const float d  = e + 1.0f;
    float r = __int_as_float(0x7EF311C3 - __float_as_int(d));  // ~3.4e-2 seed
    r = r * fmaf(-d, r, 2.0f);                // Newton 1 -> 1.2e-3
    r = r * fmaf(-d, r, 2.0f);                // Newton 2 -> 1.4e-6
    return r;
}

// R13 (deferred-h lane-pair + pipelined-xpart fill) with the i and f gate
// sigmoids moved OFF the MUFU pipe onto FMA/ALU (sigp). c'-path from z:
//   old: 3 staggered MUFUs (32) + lat 60 + tree 4 = 96
//   new: tg@60 (single MUFU, slot 0) || si,sf@~66 (parallel fixed-lat)
//        -> m@70 -> c'@74
// MUFU per step: g, o, tanh_c only. Period model 194 -> ~172.
__global__ void __launch_bounds__(NTHREADS, 1)
lstm_kernel(const float* __restrict__ x,
            const float* __restrict__ h0in,
            const float* __restrict__ c0in,
            const float* __restrict__ w_ih,
            const float* __restrict__ w_hh,
            const float* __restrict__ b_ih,
            const float* __restrict__ b_hh,
            float* __restrict__ out)
{
    const int tid  = blockIdx.x * NTHREADS + threadIdx.x;
    const int u    = tid & 1;           // hidden unit owned by this lane
    const int vv   = u ^ 1;             // partner's unit
    const int pair = tid >> 1;          // chain (batch element)

    // Gate order q: 0=i, 1=g, 2=f, 3=o (rows 0+u, 4+u, 2+u, 6+u).
    // Scales: i,f by -log2e (sigp input); g raw (MUFU tanh); o by 0.5
    // (sigma_o = 0.5*tanh(0.5 z)+0.5 on MUFU, off the critical path).
    float wi0[4], wi1[4], whO[4], whX[4], bs[4];
    const int qrow[4] = {0 + u, 4 + u, 2 + u, 6 + u};   // i, g, f, o
#pragma unroll
    for (int q = 0; q < 4; q++) {
        const int row = qrow[q];
        const float s = (q == 1) ? 1.0f : ((q == 3) ? 0.5f : NL2E);
        wi0[q] = s * __ldg(&w_ih[2*row+0]);
        wi1[q] = s * __ldg(&w_ih[2*row+1]);
        whO[q] = s * __ldg(&w_hh[2*row+u]);
        whX[q] = s * __ldg(&w_hh[2*row+vv]);
        bs[q]  = s * (__ldg(&b_ih[row]) + __ldg(&b_hh[row]));
    }

    float c = c0in[2*pair + u];

    // Deferred-h bootstrap: sigma_o := 1, tc := h0 -> first step sees h0 exactly.
    float tc = h0in[2*pair + u];
    float whOp[4], whXp[4];
#pragma unroll
    for (int q = 0; q < 4; q++) { whOp[q] = whO[q]; whXp[q] = whX[q]; }

    const float4* __restrict__ xr =
        reinterpret_cast<const float4*>(x) + (size_t)pair * (TT * 2 / 4);

    float4 buf[2][CHUNK / 2];
#pragma unroll
    for (int q = 0; q < CHUNK / 2; q++) buf[0][q] = __ldg(&xr[q]);

    // x-partials for step 0, pipelined one step ahead thereafter.
    float xp[4];
#pragma unroll
    for (int q = 0; q < 4; q++)
        xp[q] = fmaf(buf[0][0].x, wi0[q], fmaf(buf[0][0].y, wi1[q], bs[q]));

#pragma unroll 1
    for (int ch = 0; ch < TT / CHUNK; ch++) {
        const int cur = ch & 1;
        const int nb  = cur ^ 1;
        if (ch + 1 < TT / CHUNK) {
#pragma unroll
            for (int q = 0; q < CHUNK / 2; q++)
                buf[nb][q] = __ldg(&xr[(ch + 1) * (CHUNK / 2) + q]);
        }
#pragma unroll
        for (int s2 = 0; s2 < CHUNK / 2; s2++) {
            const float4 v4 = buf[cur][s2];
#pragma unroll
            for (int half = 0; half < 2; half++) {
                // x of the NEXT step (pipelined xpart computed in the fill
                // window; on the final step the result is never consumed).
                float nx0, nx1;
                if (half == 0)            { nx0 = v4.z;             nx1 = v4.w; }
                else if (s2 + 1 < CHUNK/2){ nx0 = buf[cur][s2+1].x; nx1 = buf[cur][s2+1].y; }
                else                      { nx0 = buf[nb][0].x;     nx1 = buf[nb][0].y; }

                // ---- critical path ----
                const float tc_oth = __shfl_xor_sync(0xffffffffu, tc, 1);

                float z[4];
#pragma unroll
                for (int q = 0; q < 4; q++) {
                    float t = fmaf(tc, whOp[q], xp[q]);
                    z[q] = fmaf(tc_oth, whXp[q], t);
                }

                // MUFU: g first (c-path), o second (prep path).
                const float tg = tanh_ap(z[1]);
                const float to = tanh_ap(z[3]);

                // i, f sigmoids on the FMA/ALU pipes — parallel, no stagger.
                const float si = sigp(z[0]);
                const float sf = sigp(z[2]);

                // c' = sf*c + si*tg
                const float m = si * tg;
                c = fmaf(sf, c, m);

                tc = tanh_ap(c);     // MUFU; fill window hides its latency

                // ---- fill window (off-path) ----
                const float so     = fmaf(0.5f, to, 0.5f);
                const float so_oth = __shfl_xor_sync(0xffffffffu, so, 1);
#pragma unroll
                for (int q = 0; q < 4; q++) {
                    whOp[q] = whO[q] * so;
                    whXp[q] = whX[q] * so_oth;
                }
#pragma unroll
                for (int q = 0; q < 4; q++)
                    xp[q] = fmaf(nx0, wi0[q], fmaf(nx1, wi1[q], bs[q]));
            }
        }
    }

    out[2*pair + u] = c;
}

extern "C" void kernel_launch(void* const* d_in, const int* in_sizes, int n_in,
                              void* d_out, int out_size) {
    const float* x    = (const float*)d_in[0];
    const float* h0   = (const float*)d_in[1];
    const float* c0   = (const float*)d_in[2];
    const float* w_ih = (const float*)d_in[3];
    const float* w_hh = (const float*)d_in[4];
    const float* b_ih = (const float*)d_in[5];
    const float* b_hh = (const float*)d_in[6];
    lstm_kernel<<<NBLOCKS, NTHREADS>>>(x, h0, c0, w_ih, w_hh, b_ih, b_hh,
                                       (float*)d_out);
}

// round 16
// speedup vs baseline: 1.1881x; 1.1881x over previous
#include <cuda_runtime.h>

#define BB 8192
#define TT 2048
#define NTHREADS 128           // 4 warps/block -> 1 warp per SMSP
#define NBLOCKS  128           // 512 warps; lane pair per chain
#define CHUNK 8                // timesteps per prefetch chunk

__device__ __forceinline__ float tanh_ap(float x) {
    float y;
    asm("tanh.approx.f32 %0, %1;" : "=f"(y) : "f"(x));
    return y;
}

// R13 (deferred-h lane-pair + pipelined-xpart fill) + EXCHANGE-C:
// the lane pair exchanges the raw cell state c (ready 64 cyc before tanh(c))
// instead of tc = tanh(c). Each lane computes tanh of BOTH c's locally, so
// the shfl overlaps the own-tanh instead of serializing after it:
//   R13 path: c' -> tanh 64 -> shfl 26 -> cross-fma   (tc_oth @ ~90)
//   now:      c' -> {tanh own @64 || shfl 26 -> tanh oth @86} -> cross-fma
// Bitwise identical math (same values through the same ops) -> rel_err
// must equal 3.350731e-06 exactly.
// Gate issue order i,g,f,o: o last is safe now (its sigma_o prep window
// gained ~86 cyc of slack from the later cross-tap consumption).
__global__ void __launch_bounds__(NTHREADS, 1)
lstm_kernel(const float* __restrict__ x,
            const float* __restrict__ h0in,
            const float* __restrict__ c0in,
            const float* __restrict__ w_ih,
            const float* __restrict__ w_hh,
            const float* __restrict__ b_ih,
            const float* __restrict__ b_hh,
            float* __restrict__ out)
{
    const int tid  = blockIdx.x * NTHREADS + threadIdx.x;
    const int u    = tid & 1;           // hidden unit owned by this lane
    const int vv   = u ^ 1;             // partner's unit
    const int pair = tid >> 1;          // chain (batch element)

    // Gate order q: 0=i, 1=g, 2=f, 3=o (rows 0+u, 4+u, 2+u, 6+u).
    // sigma(z)=0.5*tanh(0.5z)+0.5 with 0.5 folded into weights/bias; g unscaled.
    float wi0[4], wi1[4], whO[4], whX[4], bs[4];
    const int qrow[4] = {0 + u, 4 + u, 2 + u, 6 + u};   // i, g, f, o
#pragma unroll
    for (int q = 0; q < 4; q++) {
        const int row = qrow[q];
        const float s = (q == 1) ? 1.0f : 0.5f;
        wi0[q] = s * __ldg(&w_ih[2*row+0]);
        wi1[q] = s * __ldg(&w_ih[2*row+1]);
        whO[q] = s * __ldg(&w_hh[2*row+u]);
        whX[q] = s * __ldg(&w_hh[2*row+vv]);
        bs[q]  = s * (__ldg(&b_ih[row]) + __ldg(&b_hh[row]));
    }

    float c  = c0in[2*pair + u];
    float hc = 0.5f * c;                // running 0.5*c (off critical path)

    // Deferred-h bootstrap: sigma_o := 1, and the "tanh" carriers start as
    // h0 of BOTH units (loaded directly; no exchange needed) -> step 0 sees
    // h0 exactly, as in R13.
    float tc  = h0in[2*pair + u];       // own-unit carrier
    float tcX = h0in[2*pair + vv];      // partner-unit carrier
    float whOp[4], whXp[4];
#pragma unroll
    for (int q = 0; q < 4; q++) { whOp[q] = whO[q]; whXp[q] = whX[q]; }

    const float4* __restrict__ xr =
        reinterpret_cast<const float4*>(x) + (size_t)pair * (TT * 2 / 4);

    float4 buf[2][CHUNK / 2];
#pragma unroll
    for (int q = 0; q < CHUNK / 2; q++) buf[0][q] = __ldg(&xr[q]);

    // x-partials for step 0, pipelined one step ahead thereafter.
    float xp[4];
#pragma unroll
    for (int q = 0; q < 4; q++)
        xp[q] = fmaf(buf[0][0].x, wi0[q], fmaf(buf[0][0].y, wi1[q], bs[q]));

#pragma unroll 1
    for (int ch = 0; ch < TT / CHUNK; ch++) {
        const int cur = ch & 1;
        const int nb  = cur ^ 1;
        if (ch + 1 < TT / CHUNK) {
#pragma unroll
            for (int q = 0; q < CHUNK / 2; q++)
                buf[nb][q] = __ldg(&xr[(ch + 1) * (CHUNK / 2) + q]);
        }
#pragma unroll
        for (int s2 = 0; s2 < CHUNK / 2; s2++) {
            const float4 v4 = buf[cur][s2];
#pragma unroll
            for (int half = 0; half < 2; half++) {
                // x of the NEXT step (consumed only by the pipelined xpart
                // in the fill window; garbage-but-unused on the final step).
                float nx0, nx1;
                if (half == 0)            { nx0 = v4.z;             nx1 = v4.w; }
                else if (s2 + 1 < CHUNK/2){ nx0 = buf[cur][s2+1].x; nx1 = buf[cur][s2+1].y; }
                else                      { nx0 = buf[nb][0].x;     nx1 = buf[nb][0].y; }

                // ---- critical path ----
                // z_q: xpart + own tap (tc ready first) + cross tap outermost.
                float z[4];
#pragma unroll
                for (int q = 0; q < 4; q++) {
                    float t = fmaf(tc, whOp[q], xp[q]);
                    z[q] = fmaf(tcX, whXp[q], t);
                }

                // MUFU gates: c'-path i, g, f in the first slots; o last.
                const float ti = tanh_ap(z[0]);
                const float tg = tanh_ap(z[1]);
                const float tf = tanh_ap(z[2]);
                const float to = tanh_ap(z[3]);

                // c' = (0.5c)*t_f + (0.5c + sigma(i)*t_g), sigma = 0.5 t + 0.5
                const float si = fmaf(0.5f, ti, 0.5f);
                const float q0 = fmaf(si, tg, hc);
                c = fmaf(hc, tf, q0);

                // Exchange the RAW c (shfl overlaps the own tanh below).
                const float c_oth = __shfl_xor_sync(0xffffffffu, c, 1);
                tc  = tanh_ap(c);        // own tanh: issues immediately
                tcX = tanh_ap(c_oth);    // partner tanh: issues at shfl+eps

                // ---- fill window (off-path; hides tanh latency) ----
                const float so     = fmaf(0.5f, to, 0.5f);
                const float so_oth = __shfl_xor_sync(0xffffffffu, so, 1);
#pragma unroll
                for (int q = 0; q < 4; q++) {
                    whOp[q] = whO[q] * so;
                    whXp[q] = whX[q] * so_oth;
                }
                hc = 0.5f * c;
#pragma unroll
                for (int q = 0; q < 4; q++)
                    xp[q] = fmaf(nx0, wi0[q], fmaf(nx1, wi1[q], bs[q]));
            }
        }
    }

    out[2*pair + u] = c;
}

extern "C" void kernel_launch(void* const* d_in, const int* in_sizes, int n_in,
                              void* d_out, int out_size) {
    const float* x    = (const float*)d_in[0];
    const float* h0   = (const float*)d_in[1];
    const float* c0   = (const float*)d_in[2];
    const float* w_ih = (const float*)d_in[3];
    const float* w_hh = (const float*)d_in[4];
    const float* b_ih = (const float*)d_in[5];
    const float* b_hh = (const float*)d_in[6];
    lstm_kernel<<<NBLOCKS, NTHREADS>>>(x, h0, c0, w_ih, w_hh, b_ih, b_hh,
                                       (float*)d_out);
}

// round 17
// speedup vs baseline: 1.2238x; 1.0300x over previous
#include <cuda_runtime.h>

#define BB 8192
#define TT 2048
#define NTHREADS 128           // 4 warps/block -> 1 warp per SMSP
#define NBLOCKS  128           // 512 warps; lane pair per chain
#define CHUNK 8                // timesteps per prefetch chunk

__device__ __forceinline__ float tanh_ap(float x) {
    float y;
    asm("tanh.approx.f32 %0, %1;" : "=f"(y) : "f"(x));
    return y;
}

// R13 (deferred-h lane-pair, pipelined xpart) with the FILL SPLIT ACROSS
// BOTH dependency-wait windows:
//   window 1 (gate wait): after issuing the 4 gate MUFUs, program order now
//     holds the next-step xpart fmas + hc -> warp keeps issuing instead of
//     sleeping until the c-tree consumes ti (~60 cyc later).
//   window 2 (tanh(c) wait): sigma_o weight prep + so-shfl (needs to/so,
//     which only exist in this window anyway).
// Same instruction SET as R13, order only -> results bitwise identical
// (rel_err must be exactly 3.350731e-06).
__global__ void __launch_bounds__(NTHREADS, 1)
lstm_kernel(const float* __restrict__ x,
            const float* __restrict__ h0in,
            const float* __restrict__ c0in,
            const float* __restrict__ w_ih,
            const float* __restrict__ w_hh,
            const float* __restrict__ b_ih,
            const float* __restrict__ b_hh,
            float* __restrict__ out)
{
    const int tid  = blockIdx.x * NTHREADS + threadIdx.x;
    const int u    = tid & 1;           // hidden unit owned by this lane
    const int vv   = u ^ 1;             // partner's unit
    const int pair = tid >> 1;          // chain (batch element)

    // Gate order q: 0=o, 1=i, 2=g, 3=f (rows 6+u, 0+u, 4+u, 2+u) — R13's
    // measured-best MUFU order (o first; o-last regressed in R12).
    // sigma(z)=0.5*tanh(0.5z)+0.5 with 0.5 folded into weights/bias; g unscaled.
    float wi0[4], wi1[4], whO[4], whX[4], bs[4];
    const int qrow[4] = {6 + u, 0 + u, 4 + u, 2 + u};   // o, i, g, f
#pragma unroll
    for (int q = 0; q < 4; q++) {
        const int row = qrow[q];
        const float s = (q == 2) ? 1.0f : 0.5f;
        wi0[q] = s * __ldg(&w_ih[2*row+0]);
        wi1[q] = s * __ldg(&w_ih[2*row+1]);
        whO[q] = s * __ldg(&w_hh[2*row+u]);
        whX[q] = s * __ldg(&w_hh[2*row+vv]);
        bs[q]  = s * (__ldg(&b_ih[row]) + __ldg(&b_hh[row]));
    }

    float c  = c0in[2*pair + u];
    float hc = 0.5f * c;                // running 0.5*c (off critical path)

    // Deferred-h bootstrap: sigma_o := 1, tc := h0 -> first step sees h0 exactly.
    float tc = h0in[2*pair + u];
    float whOp[4], whXp[4];
#pragma unroll
    for (int q = 0; q < 4; q++) { whOp[q] = whO[q]; whXp[q] = whX[q]; }

    const float4* __restrict__ xr =
        reinterpret_cast<const float4*>(x) + (size_t)pair * (TT * 2 / 4);

    float4 buf[2][CHUNK / 2];
#pragma unroll
    for (int q = 0; q < CHUNK / 2; q++) buf[0][q] = __ldg(&xr[q]);

    // x-partials for step 0, pipelined one step ahead thereafter.
    float xp[4];
#pragma unroll
    for (int q = 0; q < 4; q++)
        xp[q] = fmaf(buf[0][0].x, wi0[q], fmaf(buf[0][0].y, wi1[q], bs[q]));

#pragma unroll 1
    for (int ch = 0; ch < TT / CHUNK; ch++) {
        const int cur = ch & 1;
        const int nb  = cur ^ 1;
        if (ch + 1 < TT / CHUNK) {
#pragma unroll
            for (int q = 0; q < CHUNK / 2; q++)
                buf[nb][q] = __ldg(&xr[(ch + 1) * (CHUNK / 2) + q]);
        }
#pragma unroll
        for (int s2 = 0; s2 < CHUNK / 2; s2++) {
            const float4 v4 = buf[cur][s2];
#pragma unroll
            for (int half = 0; half < 2; half++) {
                // x of the NEXT step (consumed only by the pipelined xpart;
                // garbage-but-unused on the very last step).
                float nx0, nx1;
                if (half == 0)            { nx0 = v4.z;             nx1 = v4.w; }
                else if (s2 + 1 < CHUNK/2){ nx0 = buf[cur][s2+1].x; nx1 = buf[cur][s2+1].y; }
                else                      { nx0 = buf[nb][0].x;     nx1 = buf[nb][0].y; }

                // ---- critical path head ----
                const float tc_oth = __shfl_xor_sync(0xffffffffu, tc, 1);

                float z[4];
#pragma unroll
                for (int q = 0; q < 4; q++) {
                    float t = fmaf(tc, whOp[q], xp[q]);
                    z[q] = fmaf(tc_oth, whXp[q], t);
                }

                // Gate MUFUs: o, i, g, f (R13 order).
                const float to = tanh_ap(z[0]);
                const float ti = tanh_ap(z[1]);
                const float tg = tanh_ap(z[2]);
                const float tf = tanh_ap(z[3]);

                // ---- fill window 1 (gate-tanh wait): next xpart + hc ----
                float nxp[4];
#pragma unroll
                for (int q = 0; q < 4; q++)
                    nxp[q] = fmaf(nx0, wi0[q], fmaf(nx1, wi1[q], bs[q]));
                const float hc_cur = hc;
                hc = 0.0f;  // renamed below; keeps hc's producer early

                // ---- c-tree (consumes gate results) ----
                const float si = fmaf(0.5f, ti, 0.5f);
                const float q0 = fmaf(si, tg, hc_cur);
                c = fmaf(hc_cur, tf, q0);

                tc = tanh_ap(c);     // critical path tail

                // ---- fill window 2 (tanh(c) wait): sigma_o prep ----
                const float so     = fmaf(0.5f, to, 0.5f);
                const float so_oth = __shfl_xor_sync(0xffffffffu, so, 1);
#pragma unroll
                for (int q = 0; q < 4; q++) {
                    whOp[q] = whO[q] * so;
                    whXp[q] = whX[q] * so_oth;
                }
                hc = 0.5f * c;
#pragma unroll
                for (int q = 0; q < 4; q++) xp[q] = nxp[q];
            }
        }
    }

    out[2*pair + u] = c;
}

extern "C" void kernel_launch(void* const* d_in, const int* in_sizes, int n_in,
                              void* d_out, int out_size) {
    const float* x    = (const float*)d_in[0];
    const float* h0   = (const float*)d_in[1];
    const float* c0   = (const float*)d_in[2];
    const float* w_ih = (const float*)d_in[3];
    const float* w_hh = (const float*)d_in[4];
    const float* b_ih = (const float*)d_in[5];
    const float* b_hh = (const float*)d_in[6];
    lstm_kernel<<<NBLOCKS, NTHREADS>>>(x, h0, c0, w_ih, w_hh, b_ih, b_hh,
                                       (float*)d_out);
}